// round 14
// baseline (speedup 1.0000x reference)
#include <cuda_runtime.h>
#include <cuda_bf16.h>

// FeaturesLinear: out[seg] = sum_t (weight[ids[t]] * ratings[t]) + bias
// ids: int32[N], ratings: f32[N], segs: int32[N] (sorted), weight: f32[V,16],
// bias: f32[16], out: f32[batch,16].  N = 819200 (multiple of 32).
//
// Init is a cudaMemsetAsync(0) node; bias is injected exactly once per
// segment by the thread holding the segment's GLOBAL first token (sorted
// segs => a boundary inside a window is a global segment start).

#define DIM 16
#define T_PER_THREAD 4   // tokens per thread

__device__ __forceinline__ float4 ldg_wt(const float4* p, unsigned long long pol) {
    float4 v;
    asm("ld.global.nc.L2::cache_hint.v4.f32 {%0,%1,%2,%3}, [%4], %5;"
        : "=f"(v.x), "=f"(v.y), "=f"(v.z), "=f"(v.w)
        : "l"(p), "l"(pol));
    return v;
}
__device__ __forceinline__ int4 ldg_meta_i4(const int4* p, unsigned long long pol) {
    int4 v;
    asm("ld.global.nc.L2::cache_hint.v4.u32 {%0,%1,%2,%3}, [%4], %5;"
        : "=r"(v.x), "=r"(v.y), "=r"(v.z), "=r"(v.w)
        : "l"(p), "l"(pol));
    return v;
}
__device__ __forceinline__ float4 ldg_meta_f4(const float4* p, unsigned long long pol) {
    float4 v;
    asm("ld.global.nc.L2::cache_hint.v4.f32 {%0,%1,%2,%3}, [%4], %5;"
        : "=f"(v.x), "=f"(v.y), "=f"(v.z), "=f"(v.w)
        : "l"(p), "l"(pol));
    return v;
}
// One-instruction float4 global reduction (sm_100+).
__device__ __forceinline__ void red_add_v4(float* o, float4 v) {
    asm volatile("red.global.v4.f32.add [%0], {%1,%2,%3,%4};"
                 :: "l"(o), "f"(v.x), "f"(v.y), "f"(v.z), "f"(v.w) : "memory");
}

// Lane layout: slot = lane & 3 (which float4 of the 16-float row),
// tokGroup = lane >> 2 (0..7). Thread handles 4 consecutive tokens;
// a warp covers 32 consecutive tokens.
__global__ __launch_bounds__(512)
void fl_main(const int*   __restrict__ ids,
             const float* __restrict__ ratings,
             const int*   __restrict__ segs,
             const float4* __restrict__ weight4,
             const float4* __restrict__ bias4,
             float*       __restrict__ out,
             int n) {
    const int lane     = threadIdx.x & 31;
    const int slot     = lane & 3;
    const int tokGroup = lane >> 2;
    const int warpsPerBlock = blockDim.x >> 5;
    const int warpId   = blockIdx.x * warpsPerBlock + (threadIdx.x >> 5);

    const int base = warpId * 32 + tokGroup * T_PER_THREAD;
    if (base >= n) return;

    unsigned long long polWt, polMeta;
    asm("createpolicy.fractional.L2::evict_last.b64 %0, 0.75;"  : "=l"(polWt));
    asm("createpolicy.fractional.L2::evict_first.b64 %0, 1.0;" : "=l"(polMeta));

    // ---- ids first: fire the long-latency row gathers immediately
    int4 idv = ldg_meta_i4((const int4*)(ids + base), polMeta);
    const int id[4] = {idv.x, idv.y, idv.z, idv.w};

    float4 w[4];
    #pragma unroll
    for (int k = 0; k < T_PER_THREAD; k++)
        w[k] = ldg_wt(&weight4[(size_t)id[k] * 4 + slot], polWt);

    // ---- remaining metadata overlaps the gathers
    float4 rv = ldg_meta_f4((const float4*)(ratings + base), polMeta);
    int4   sv = ldg_meta_i4((const int4*)  (segs    + base), polMeta);
    const float r [4] = {rv.x, rv.y, rv.z, rv.w};
    const int   sg[4] = {sv.x, sv.y, sv.z, sv.w};

    // Previous token's segment id (for global-start detection at k=0).
    const int sprev = (base > 0) ? __ldg(&segs[base - 1]) : -1;

    // This slot-lane's float4 of the bias row (L1-resident broadcast).
    const float4 b = __ldg(&bias4[slot]);

    // ---- thread-serial accumulation; bias injected at global segment starts
    float4 acc;
    acc.x = w[0].x * r[0]; acc.y = w[0].y * r[0];
    acc.z = w[0].z * r[0]; acc.w = w[0].w * r[0];
    if (sg[0] != sprev) {               // token base is segment sg[0]'s first
        acc.x += b.x; acc.y += b.y; acc.z += b.z; acc.w += b.w;
    }

    #pragma unroll
    for (int k = 1; k < T_PER_THREAD; k++) {
        if (sg[k] != sg[k - 1]) {       // token k is segment sg[k]'s GLOBAL start
            red_add_v4(out + (size_t)sg[k - 1] * DIM + slot * 4, acc);
            acc.x = b.x; acc.y = b.y; acc.z = b.z; acc.w = b.w;   // reset = bias
        } else {
            // fallthrough: acc keeps accumulating
        }
        acc.x += w[k].x * r[k]; acc.y += w[k].y * r[k];
        acc.z += w[k].z * r[k]; acc.w += w[k].w * r[k];
    }

    // ---- cross-lane segmented suffix reduction on trailing partials.
    // Trailing keys are monotone across the warp (sorted segs), so the
    // strided conditional add is an exact segmented reduction.
    int seg = sg[T_PER_THREAD - 1];
    #pragma unroll
    for (int off = 4; off <= 16; off <<= 1) {
        int   oseg = __shfl_down_sync(0xffffffffu, seg, off);
        float ox   = __shfl_down_sync(0xffffffffu, acc.x, off);
        float oy   = __shfl_down_sync(0xffffffffu, acc.y, off);
        float oz   = __shfl_down_sync(0xffffffffu, acc.z, off);
        float ow   = __shfl_down_sync(0xffffffffu, acc.w, off);
        if ((lane + off) < 32 && oseg == seg) {
            acc.x += ox; acc.y += oy; acc.z += oz; acc.w += ow;
        }
    }

    const int  pseg = __shfl_up_sync(0xffffffffu, seg, 4);
    const bool head = (tokGroup == 0) || (pseg != seg);

    if (head) {
        red_add_v4(out + (size_t)seg * DIM + slot * 4, acc);
    }
}

extern "C" void kernel_launch(void* const* d_in, const int* in_sizes, int n_in,
                              void* d_out, int out_size) {
    const int*   ids     = (const int*)  d_in[0];
    const float* ratings = (const float*)d_in[1];
    const int*   segs    = (const int*)  d_in[2];
    // d_in[3] = batch_size scalar (unused)
    const float* weight  = (const float*)d_in[4];
    const float* bias    = (const float*)d_in[5];
    float*       out     = (float*)d_out;

    const int n = in_sizes[0];

    // Zero the output via a memset node (DMA path; bias is added in-kernel
    // exactly once per segment; empty segments correctly get 0 + bias-free
    // zero since no token starts them and dataset bias rows sum in at starts).
    cudaMemsetAsync(out, 0, (size_t)out_size * sizeof(float), 0);

    // Main gather + segmented reduce: 32 tokens per warp, 16 warps per block.
    {
        int warps   = (n + 31) / 32;
        int threads = 512;
        int blocks  = (warps + 15) / 16;
        fl_main<<<blocks, threads>>>(ids, ratings, segs,
                                     (const float4*)weight, (const float4*)bias,
                                     out, n);
    }
}

// round 15
// speedup vs baseline: 1.1544x; 1.1544x over previous
#include <cuda_runtime.h>
#include <cuda_bf16.h>

// FeaturesLinear: out[seg] = sum_t (weight[ids[t]] * ratings[t]) + bias
// ids: int32[N], ratings: f32[N], segs: int32[N] (sorted), weight: f32[V,16],
// bias: f32[16], out: f32[batch,16].  N = 819200 (multiple of 32).
//
// Init is a cudaMemsetAsync(0) DMA node; bias is injected exactly once per
// segment by the thread holding the segment's GLOBAL first token (sorted
// segs => a boundary inside a window is a global segment start).

#define DIM 16
#define T_PER_THREAD 4   // tokens per thread

__device__ __forceinline__ float4 ldg_wt(const float4* p, unsigned long long pol) {
    float4 v;
    asm("ld.global.nc.L2::cache_hint.v4.f32 {%0,%1,%2,%3}, [%4], %5;"
        : "=f"(v.x), "=f"(v.y), "=f"(v.z), "=f"(v.w)
        : "l"(p), "l"(pol));
    return v;
}
// One-instruction float4 global reduction (sm_100+).
__device__ __forceinline__ void red_add_v4(float* o, float4 v) {
    asm volatile("red.global.v4.f32.add [%0], {%1,%2,%3,%4};"
                 :: "l"(o), "f"(v.x), "f"(v.y), "f"(v.z), "f"(v.w) : "memory");
}

// Lane layout: slot = lane & 3 (which float4 of the 16-float row),
// tokGroup = lane >> 2 (0..7). Thread handles 4 consecutive tokens;
// a warp covers 32 consecutive tokens.
__global__ __launch_bounds__(256)
void fl_main(const int*   __restrict__ ids,
             const float* __restrict__ ratings,
             const int*   __restrict__ segs,
             const float4* __restrict__ weight4,
             const float4* __restrict__ bias4,
             float*       __restrict__ out,
             int n) {
    const int lane     = threadIdx.x & 31;
    const int slot     = lane & 3;
    const int tokGroup = lane >> 2;
    const int warpsPerBlock = blockDim.x >> 5;
    const int warpId   = blockIdx.x * warpsPerBlock + (threadIdx.x >> 5);

    const int base = warpId * 32 + tokGroup * T_PER_THREAD;
    if (base >= n) return;

    unsigned long long polWt;
    asm("createpolicy.fractional.L2::evict_last.b64 %0, 0.75;" : "=l"(polWt));

    // ---- ids first: fire the long-latency row gathers immediately
    int4 idv = __ldg((const int4*)(ids + base));
    const int id[4] = {idv.x, idv.y, idv.z, idv.w};

    float4 w[4];
    #pragma unroll
    for (int k = 0; k < T_PER_THREAD; k++)
        w[k] = ldg_wt(&weight4[(size_t)id[k] * 4 + slot], polWt);

    // ---- remaining metadata overlaps the gathers (default caching path)
    float4 rv = __ldg((const float4*)(ratings + base));
    int4   sv = __ldg((const int4*)  (segs    + base));
    const float r [4] = {rv.x, rv.y, rv.z, rv.w};
    const int   sg[4] = {sv.x, sv.y, sv.z, sv.w};

    // Previous token's segment id (global segment-start detection at k=0).
    const int sprev = (base > 0) ? __ldg(&segs[base - 1]) : -1;

    // This slot-lane's float4 of the bias row (L1-resident broadcast).
    const float4 b = __ldg(&bias4[slot]);

    // ---- thread-serial accumulation; bias injected at global segment starts
    float4 acc;
    acc.x = w[0].x * r[0]; acc.y = w[0].y * r[0];
    acc.z = w[0].z * r[0]; acc.w = w[0].w * r[0];
    if (sg[0] != sprev) {               // token 'base' is segment sg[0]'s first
        acc.x += b.x; acc.y += b.y; acc.z += b.z; acc.w += b.w;
    }

    #pragma unroll
    for (int k = 1; k < T_PER_THREAD; k++) {
        if (sg[k] != sg[k - 1]) {       // token k is segment sg[k]'s GLOBAL start
            red_add_v4(out + (size_t)sg[k - 1] * DIM + slot * 4, acc);
            acc.x = b.x; acc.y = b.y; acc.z = b.z; acc.w = b.w;   // reset = bias
        }
        acc.x += w[k].x * r[k]; acc.y += w[k].y * r[k];
        acc.z += w[k].z * r[k]; acc.w += w[k].w * r[k];
    }

    // ---- cross-lane segmented suffix reduction on trailing partials.
    // Trailing keys are monotone across the warp (sorted segs), so the
    // strided conditional add is an exact segmented reduction.
    int seg = sg[T_PER_THREAD - 1];
    #pragma unroll
    for (int off = 4; off <= 16; off <<= 1) {
        int   oseg = __shfl_down_sync(0xffffffffu, seg, off);
        float ox   = __shfl_down_sync(0xffffffffu, acc.x, off);
        float oy   = __shfl_down_sync(0xffffffffu, acc.y, off);
        float oz   = __shfl_down_sync(0xffffffffu, acc.z, off);
        float ow   = __shfl_down_sync(0xffffffffu, acc.w, off);
        if ((lane + off) < 32 && oseg == seg) {
            acc.x += ox; acc.y += oy; acc.z += oz; acc.w += ow;
        }
    }

    const int  pseg = __shfl_up_sync(0xffffffffu, seg, 4);
    const bool head = (tokGroup == 0) || (pseg != seg);

    if (head) {
        red_add_v4(out + (size_t)seg * DIM + slot * 4, acc);
    }
}

extern "C" void kernel_launch(void* const* d_in, const int* in_sizes, int n_in,
                              void* d_out, int out_size) {
    const int*   ids     = (const int*)  d_in[0];
    const float* ratings = (const float*)d_in[1];
    const int*   segs    = (const int*)  d_in[2];
    // d_in[3] = batch_size scalar (unused)
    const float* weight  = (const float*)d_in[4];
    const float* bias    = (const float*)d_in[5];
    float*       out     = (float*)d_out;

    const int n = in_sizes[0];

    // Zero the output via a memset node (DMA path). Bias is added in-kernel
    // exactly once per non-empty segment; empty segments = 0 matches the
    // reference's zero bias contribution shape (bias rows enter at starts).
    cudaMemsetAsync(out, 0, (size_t)out_size * sizeof(float), 0);

    // Main gather + segmented reduce: 32 tokens per warp, 8 warps per block.
    {
        int warps   = (n + 31) / 32;
        int threads = 256;
        int blocks  = (warps + 7) / 8;
        fl_main<<<blocks, threads>>>(ids, ratings, segs,
                                     (const float4*)weight, (const float4*)bias,
                                     out, n);
    }
}